// round 2
// baseline (speedup 1.0000x reference)
#include <cuda_runtime.h>

#define B_  2
#define S_  2048
#define E_  1024
#define H_  16
#define D_  64
#define BS_ (B_*S_)

// Scratch (no cudaMalloc allowed): Q,K,V as [B,H,S,D]; ctx as [B,S,H,D] (=concat layout)
__device__ float g_q[(size_t)B_*H_*S_*D_];
__device__ float g_k[(size_t)B_*H_*S_*D_];
__device__ float g_v[(size_t)B_*H_*S_*D_];
__device__ float g_ctx[(size_t)B_*S_*H_*D_];

// ---------------------------------------------------------------------------
// Kernel A: QKV projection. out[b,h,s,d] = sum_e x[b,s,e]*W[h,e,d] + bias[h,d]
// grid: (BS/64, H, 3), block 256 (16x16 threads, 4x4 microtile)
// ---------------------------------------------------------------------------
__global__ __launch_bounds__(256) void qkv_kernel(
    const float* __restrict__ x,
    const float* __restrict__ Wq, const float* __restrict__ bq,
    const float* __restrict__ Wk, const float* __restrict__ bk,
    const float* __restrict__ Wv, const float* __restrict__ bv)
{
    __shared__ float Xs[16][64];  // [kk][row]  (x chunk, transposed)
    __shared__ float Ws[16][64];  // [kk][d]

    const float* W; const float* bias; float* out;
    switch (blockIdx.z) {
        case 0:  W = Wq; bias = bq; out = g_q; break;
        case 1:  W = Wk; bias = bk; out = g_k; break;
        default: W = Wv; bias = bv; out = g_v; break;
    }
    const int h   = blockIdx.y;
    const int m0  = blockIdx.x * 64;
    const int tid = threadIdx.x;
    const int tx  = tid & 15, ty = tid >> 4;

    const float* Wh = W + (size_t)h * E_ * D_;

    float acc[4][4] = {};

    const int lr  = tid >> 2;        // 0..63  (x row)
    const int lc4 = (tid & 3) * 4;   // 0,4,8,12 (x col group within chunk)
    const int wd  = tid & 63;        // d for W load
    const int wk  = tid >> 6;        // 0..3 kk base for W load

    for (int e0 = 0; e0 < E_; e0 += 16) {
        __syncthreads();
        float4 xv = *(const float4*)&x[(size_t)(m0 + lr) * E_ + e0 + lc4];
        Xs[lc4 + 0][lr] = xv.x;
        Xs[lc4 + 1][lr] = xv.y;
        Xs[lc4 + 2][lr] = xv.z;
        Xs[lc4 + 3][lr] = xv.w;
        #pragma unroll
        for (int s = 0; s < 4; s++)
            Ws[wk + 4*s][wd] = Wh[(size_t)(e0 + wk + 4*s) * D_ + wd];
        __syncthreads();

        #pragma unroll
        for (int kk = 0; kk < 16; kk++) {
            float4 a = *(const float4*)&Xs[kk][4*ty];
            float4 b = *(const float4*)&Ws[kk][4*tx];
            float av[4] = {a.x, a.y, a.z, a.w};
            float bw[4] = {b.x, b.y, b.z, b.w};
            #pragma unroll
            for (int i = 0; i < 4; i++)
                #pragma unroll
                for (int j = 0; j < 4; j++)
                    acc[i][j] = fmaf(av[i], bw[j], acc[i][j]);
        }
    }

    #pragma unroll
    for (int i = 0; i < 4; i++) {
        int m  = m0 + 4*ty + i;
        int bb = m >> 11;          // / S_
        int sl = m & (S_ - 1);
        float4 o;
        o.x = acc[i][0] + bias[h*D_ + 4*tx + 0];
        o.y = acc[i][1] + bias[h*D_ + 4*tx + 1];
        o.z = acc[i][2] + bias[h*D_ + 4*tx + 2];
        o.w = acc[i][3] + bias[h*D_ + 4*tx + 3];
        *(float4*)&out[(((size_t)bb*H_ + h)*S_ + sl)*D_ + 4*tx] = o;
    }
}

// ---------------------------------------------------------------------------
// Kernel B: flash attention per (b,h, 64-row q tile). grid (S/64, H, B), 256 thr
// Online softmax with running max/sum; mask applied as reference (-1e9).
// ---------------------------------------------------------------------------
__global__ __launch_bounds__(256) void attn_kernel(const int* __restrict__ mask)
{
    __shared__ float Qs [64][64];  // [d][qrow]
    __shared__ float KPs[64][64];  // phase 1: K as [d][krow]; phase 2: P as [krow][qrow]
    __shared__ float Vs [64][64];  // [krow][d]

    const int q0 = blockIdx.x * 64;
    const int h  = blockIdx.y;
    const int b  = blockIdx.z;

    const size_t base = ((size_t)b*H_ + h) * S_ * D_;
    const float* Q = g_q + base;
    const float* K = g_k + base;
    const float* V = g_v + base;
    const int*   M = mask + (size_t)b * S_ * S_;

    const int tid = threadIdx.x;
    const int tx  = tid & 15, ty = tid >> 4;

    const int lr  = tid >> 2;        // 0..63 (row for transposed loads)
    const int ld0 = (tid & 3) * 16;  // d base (16 d values per thread)
    const int vd4 = (tid & 15) * 4;  // V load col group
    const int vr  = tid >> 4;        // V load row base

    // Q tile, transposed
    #pragma unroll
    for (int u = 0; u < 4; u++) {
        float4 qv = *(const float4*)&Q[(size_t)(q0 + lr) * D_ + ld0 + 4*u];
        Qs[ld0 + 4*u + 0][lr] = qv.x;
        Qs[ld0 + 4*u + 1][lr] = qv.y;
        Qs[ld0 + 4*u + 2][lr] = qv.z;
        Qs[ld0 + 4*u + 3][lr] = qv.w;
    }

    float m_i[4], l_i[4], acc[4][4];
    #pragma unroll
    for (int i = 0; i < 4; i++) {
        m_i[i] = -1e30f; l_i[i] = 0.f;
        #pragma unroll
        for (int j = 0; j < 4; j++) acc[i][j] = 0.f;
    }

    for (int k0 = 0; k0 < S_; k0 += 64) {
        __syncthreads();   // prior-iter KPs/Vs reads done; also fences Qs load on iter 0
        // K tile, transposed
        #pragma unroll
        for (int u = 0; u < 4; u++) {
            float4 kv = *(const float4*)&K[(size_t)(k0 + lr) * D_ + ld0 + 4*u];
            KPs[ld0 + 4*u + 0][lr] = kv.x;
            KPs[ld0 + 4*u + 1][lr] = kv.y;
            KPs[ld0 + 4*u + 2][lr] = kv.z;
            KPs[ld0 + 4*u + 3][lr] = kv.w;
        }
        // V tile, direct
        #pragma unroll
        for (int t = 0; t < 4; t++)
            *(float4*)&Vs[vr + 16*t][vd4] =
                *(const float4*)&V[(size_t)(k0 + vr + 16*t) * D_ + vd4];
        __syncthreads();

        // scores s = Q K^T
        float s[4][4] = {};
        #pragma unroll 16
        for (int d = 0; d < 64; d++) {
            float4 a = *(const float4*)&Qs[d][4*ty];
            float4 c = *(const float4*)&KPs[d][4*tx];
            float av[4] = {a.x, a.y, a.z, a.w};
            float cv[4] = {c.x, c.y, c.z, c.w};
            #pragma unroll
            for (int i = 0; i < 4; i++)
                #pragma unroll
                for (int j = 0; j < 4; j++)
                    s[i][j] = fmaf(av[i], cv[j], s[i][j]);
        }

        // mask + scale + online softmax update
        float p[4][4];
        #pragma unroll
        for (int i = 0; i < 4; i++) {
            int4 mv = *(const int4*)&M[(size_t)(q0 + 4*ty + i) * S_ + k0 + 4*tx];
            float sv[4];
            sv[0] = mv.x ? s[i][0] * 0.125f : -1e9f;
            sv[1] = mv.y ? s[i][1] * 0.125f : -1e9f;
            sv[2] = mv.z ? s[i][2] * 0.125f : -1e9f;
            sv[3] = mv.w ? s[i][3] * 0.125f : -1e9f;
            float mx = fmaxf(fmaxf(sv[0], sv[1]), fmaxf(sv[2], sv[3]));
            #pragma unroll
            for (int off = 1; off < 16; off <<= 1)
                mx = fmaxf(mx, __shfl_xor_sync(0xffffffffu, mx, off));
            float mnew = fmaxf(m_i[i], mx);
            float f    = __expf(m_i[i] - mnew);
            float sum  = 0.f;
            #pragma unroll
            for (int j = 0; j < 4; j++) { p[i][j] = __expf(sv[j] - mnew); sum += p[i][j]; }
            #pragma unroll
            for (int off = 1; off < 16; off <<= 1)
                sum += __shfl_xor_sync(0xffffffffu, sum, off);
            l_i[i] = l_i[i] * f + sum;
            m_i[i] = mnew;
            #pragma unroll
            for (int j = 0; j < 4; j++) acc[i][j] *= f;
        }

        __syncthreads();   // K reads of KPs done
        // store P transposed: KPs[kcol][qrow]
        #pragma unroll
        for (int j = 0; j < 4; j++) {
            float4 w = make_float4(p[0][j], p[1][j], p[2][j], p[3][j]);
            *(float4*)&KPs[4*tx + j][4*ty] = w;
        }
        __syncthreads();

        // acc += P V
        #pragma unroll 16
        for (int k = 0; k < 64; k++) {
            float4 a  = *(const float4*)&KPs[k][4*ty];
            float4 vv = *(const float4*)&Vs[k][4*tx];
            float av[4] = {a.x, a.y, a.z, a.w};
            float vw[4] = {vv.x, vv.y, vv.z, vv.w};
            #pragma unroll
            for (int i = 0; i < 4; i++)
                #pragma unroll
                for (int j = 0; j < 4; j++)
                    acc[i][j] = fmaf(av[i], vw[j], acc[i][j]);
        }
    }

    // normalize and write ctx[b, s, h, d]
    #pragma unroll
    for (int i = 0; i < 4; i++) {
        float inv = 1.0f / l_i[i];
        float4 o = make_float4(acc[i][0]*inv, acc[i][1]*inv, acc[i][2]*inv, acc[i][3]*inv);
        *(float4*)&g_ctx[(((size_t)b*S_ + q0 + 4*ty + i)*H_ + h)*D_ + 4*tx] = o;
    }
}

// ---------------------------------------------------------------------------
// Kernel C: output projection. out[m,n] = sum_k ctx[m,k]*Wo[k,n] + bo[n]
// grid: (BS/64, E/64), block 256
// ---------------------------------------------------------------------------
__global__ __launch_bounds__(256) void oproj_kernel(
    const float* __restrict__ Wo, const float* __restrict__ bo,
    float* __restrict__ out)
{
    __shared__ float Xs[16][64];
    __shared__ float Ws[16][64];

    const int m0  = blockIdx.x * 64;
    const int n0  = blockIdx.y * 64;
    const int tid = threadIdx.x;
    const int tx  = tid & 15, ty = tid >> 4;

    float acc[4][4] = {};

    const int lr  = tid >> 2;
    const int lc4 = (tid & 3) * 4;
    const int wd  = tid & 63;
    const int wk  = tid >> 6;

    const float* ctx = g_ctx;

    for (int e0 = 0; e0 < E_; e0 += 16) {
        __syncthreads();
        float4 xv = *(const float4*)&ctx[(size_t)(m0 + lr) * E_ + e0 + lc4];
        Xs[lc4 + 0][lr] = xv.x;
        Xs[lc4 + 1][lr] = xv.y;
        Xs[lc4 + 2][lr] = xv.z;
        Xs[lc4 + 3][lr] = xv.w;
        #pragma unroll
        for (int s = 0; s < 4; s++)
            Ws[wk + 4*s][wd] = Wo[(size_t)(e0 + wk + 4*s) * E_ + n0 + wd];
        __syncthreads();

        #pragma unroll
        for (int kk = 0; kk < 16; kk++) {
            float4 a = *(const float4*)&Xs[kk][4*ty];
            float4 b = *(const float4*)&Ws[kk][4*tx];
            float av[4] = {a.x, a.y, a.z, a.w};
            float bw[4] = {b.x, b.y, b.z, b.w};
            #pragma unroll
            for (int i = 0; i < 4; i++)
                #pragma unroll
                for (int j = 0; j < 4; j++)
                    acc[i][j] = fmaf(av[i], bw[j], acc[i][j]);
        }
    }

    #pragma unroll
    for (int i = 0; i < 4; i++) {
        int m = m0 + 4*ty + i;
        float4 o;
        o.x = acc[i][0] + bo[n0 + 4*tx + 0];
        o.y = acc[i][1] + bo[n0 + 4*tx + 1];
        o.z = acc[i][2] + bo[n0 + 4*tx + 2];
        o.w = acc[i][3] + bo[n0 + 4*tx + 3];
        *(float4*)&out[(size_t)m * E_ + n0 + 4*tx] = o;
    }
}

// ---------------------------------------------------------------------------
extern "C" void kernel_launch(void* const* d_in, const int* in_sizes, int n_in,
                              void* d_out, int out_size)
{
    const float* x    = (const float*)d_in[0];
    const int*   mask = (const int*)  d_in[1];
    const float* Wq   = (const float*)d_in[2];
    const float* bq   = (const float*)d_in[3];
    const float* Wk   = (const float*)d_in[4];
    const float* bk   = (const float*)d_in[5];
    const float* Wv   = (const float*)d_in[6];
    const float* bv   = (const float*)d_in[7];
    const float* Wo   = (const float*)d_in[8];
    const float* bo   = (const float*)d_in[9];
    float* out = (float*)d_out;

    dim3 gA(BS_/64, H_, 3);
    qkv_kernel<<<gA, 256>>>(x, Wq, bq, Wk, bk, Wv, bv);

    dim3 gB(S_/64, H_, B_);
    attn_kernel<<<gB, 256>>>(mask);

    dim3 gC(BS_/64, E_/64);
    oproj_kernel<<<gC, 256>>>(Wo, bo, out);
}

// round 3
// speedup vs baseline: 1.0014x; 1.0014x over previous
#include <cuda_runtime.h>

#define B_  2
#define S_  2048
#define E_  1024
#define H_  16
#define D_  64
#define BS_ (B_*S_)

// Scratch (no cudaMalloc allowed): Q,K,V as [B,H,S,D]; ctx as [B,S,H,D] (=concat layout)
__device__ float g_q[(size_t)B_*H_*S_*D_];
__device__ float g_k[(size_t)B_*H_*S_*D_];
__device__ float g_v[(size_t)B_*H_*S_*D_];
__device__ float g_ctx[(size_t)B_*S_*H_*D_];

// ---------------------------------------------------------------------------
// Kernel A: QKV projection. out[b,h,s,d] = sum_e x[b,s,e]*W[h,e,d] + bias[h,d]
// grid: (BS/64, H, 3), block 256 (16x16 threads, 4x4 microtile)
// ---------------------------------------------------------------------------
__global__ __launch_bounds__(256) void qkv_kernel(
    const float* __restrict__ x,
    const float* __restrict__ Wq, const float* __restrict__ bq,
    const float* __restrict__ Wk, const float* __restrict__ bk,
    const float* __restrict__ Wv, const float* __restrict__ bv)
{
    __shared__ float Xs[16][64];  // [kk][row]  (x chunk, transposed)
    __shared__ float Ws[16][64];  // [kk][d]

    const float* W; const float* bias; float* out;
    switch (blockIdx.z) {
        case 0:  W = Wq; bias = bq; out = g_q; break;
        case 1:  W = Wk; bias = bk; out = g_k; break;
        default: W = Wv; bias = bv; out = g_v; break;
    }
    const int h   = blockIdx.y;
    const int m0  = blockIdx.x * 64;
    const int tid = threadIdx.x;
    const int tx  = tid & 15, ty = tid >> 4;

    const float* Wh = W + (size_t)h * E_ * D_;

    float acc[4][4] = {};

    const int lr  = tid >> 2;        // 0..63  (x row)
    const int lc4 = (tid & 3) * 4;   // 0,4,8,12 (x col group within chunk)
    const int wd  = tid & 63;        // d for W load
    const int wk  = tid >> 6;        // 0..3 kk base for W load

    for (int e0 = 0; e0 < E_; e0 += 16) {
        __syncthreads();
        float4 xv = *(const float4*)&x[(size_t)(m0 + lr) * E_ + e0 + lc4];
        Xs[lc4 + 0][lr] = xv.x;
        Xs[lc4 + 1][lr] = xv.y;
        Xs[lc4 + 2][lr] = xv.z;
        Xs[lc4 + 3][lr] = xv.w;
        #pragma unroll
        for (int s = 0; s < 4; s++)
            Ws[wk + 4*s][wd] = Wh[(size_t)(e0 + wk + 4*s) * D_ + wd];
        __syncthreads();

        #pragma unroll
        for (int kk = 0; kk < 16; kk++) {
            float4 a = *(const float4*)&Xs[kk][4*ty];
            float4 b = *(const float4*)&Ws[kk][4*tx];
            float av[4] = {a.x, a.y, a.z, a.w};
            float bw[4] = {b.x, b.y, b.z, b.w};
            #pragma unroll
            for (int i = 0; i < 4; i++)
                #pragma unroll
                for (int j = 0; j < 4; j++)
                    acc[i][j] = fmaf(av[i], bw[j], acc[i][j]);
        }
    }

    #pragma unroll
    for (int i = 0; i < 4; i++) {
        int m  = m0 + 4*ty + i;
        int bb = m >> 11;          // / S_
        int sl = m & (S_ - 1);
        float4 o;
        o.x = acc[i][0] + bias[h*D_ + 4*tx + 0];
        o.y = acc[i][1] + bias[h*D_ + 4*tx + 1];
        o.z = acc[i][2] + bias[h*D_ + 4*tx + 2];
        o.w = acc[i][3] + bias[h*D_ + 4*tx + 3];
        *(float4*)&out[(((size_t)bb*H_ + h)*S_ + sl)*D_ + 4*tx] = o;
    }
}

// ---------------------------------------------------------------------------
// Kernel B: flash attention per (b,h, 64-row q tile). grid (S/64, H, B), 256 thr
// Online softmax with running max/sum; mask applied as reference (-1e9).
// ---------------------------------------------------------------------------
__global__ __launch_bounds__(256) void attn_kernel(const int* __restrict__ mask)
{
    __shared__ float Qs [64][64];  // [d][qrow]
    __shared__ float KPs[64][64];  // phase 1: K as [d][krow]; phase 2: P as [krow][qrow]
    __shared__ float Vs [64][64];  // [krow][d]

    const int q0 = blockIdx.x * 64;
    const int h  = blockIdx.y;
    const int b  = blockIdx.z;

    const size_t base = ((size_t)b*H_ + h) * S_ * D_;
    const float* Q = g_q + base;
    const float* K = g_k + base;
    const float* V = g_v + base;
    const int*   M = mask + (size_t)b * S_ * S_;

    const int tid = threadIdx.x;
    const int tx  = tid & 15, ty = tid >> 4;

    const int lr  = tid >> 2;        // 0..63 (row for transposed loads)
    const int ld0 = (tid & 3) * 16;  // d base (16 d values per thread)
    const int vd4 = (tid & 15) * 4;  // V load col group
    const int vr  = tid >> 4;        // V load row base

    // Q tile, transposed
    #pragma unroll
    for (int u = 0; u < 4; u++) {
        float4 qv = *(const float4*)&Q[(size_t)(q0 + lr) * D_ + ld0 + 4*u];
        Qs[ld0 + 4*u + 0][lr] = qv.x;
        Qs[ld0 + 4*u + 1][lr] = qv.y;
        Qs[ld0 + 4*u + 2][lr] = qv.z;
        Qs[ld0 + 4*u + 3][lr] = qv.w;
    }

    float m_i[4], l_i[4], acc[4][4];
    #pragma unroll
    for (int i = 0; i < 4; i++) {
        m_i[i] = -1e30f; l_i[i] = 0.f;
        #pragma unroll
        for (int j = 0; j < 4; j++) acc[i][j] = 0.f;
    }

    for (int k0 = 0; k0 < S_; k0 += 64) {
        __syncthreads();   // prior-iter KPs/Vs reads done; also fences Qs load on iter 0
        // K tile, transposed
        #pragma unroll
        for (int u = 0; u < 4; u++) {
            float4 kv = *(const float4*)&K[(size_t)(k0 + lr) * D_ + ld0 + 4*u];
            KPs[ld0 + 4*u + 0][lr] = kv.x;
            KPs[ld0 + 4*u + 1][lr] = kv.y;
            KPs[ld0 + 4*u + 2][lr] = kv.z;
            KPs[ld0 + 4*u + 3][lr] = kv.w;
        }
        // V tile, direct
        #pragma unroll
        for (int t = 0; t < 4; t++)
            *(float4*)&Vs[vr + 16*t][vd4] =
                *(const float4*)&V[(size_t)(k0 + vr + 16*t) * D_ + vd4];
        __syncthreads();

        // scores s = Q K^T
        float s[4][4] = {};
        #pragma unroll 16
        for (int d = 0; d < 64; d++) {
            float4 a = *(const float4*)&Qs[d][4*ty];
            float4 c = *(const float4*)&KPs[d][4*tx];
            float av[4] = {a.x, a.y, a.z, a.w};
            float cv[4] = {c.x, c.y, c.z, c.w};
            #pragma unroll
            for (int i = 0; i < 4; i++)
                #pragma unroll
                for (int j = 0; j < 4; j++)
                    s[i][j] = fmaf(av[i], cv[j], s[i][j]);
        }

        // mask + scale + online softmax update
        float p[4][4];
        #pragma unroll
        for (int i = 0; i < 4; i++) {
            int4 mv = *(const int4*)&M[(size_t)(q0 + 4*ty + i) * S_ + k0 + 4*tx];
            float sv[4];
            sv[0] = mv.x ? s[i][0] * 0.125f : -1e9f;
            sv[1] = mv.y ? s[i][1] * 0.125f : -1e9f;
            sv[2] = mv.z ? s[i][2] * 0.125f : -1e9f;
            sv[3] = mv.w ? s[i][3] * 0.125f : -1e9f;
            float mx = fmaxf(fmaxf(sv[0], sv[1]), fmaxf(sv[2], sv[3]));
            #pragma unroll
            for (int off = 1; off < 16; off <<= 1)
                mx = fmaxf(mx, __shfl_xor_sync(0xffffffffu, mx, off));
            float mnew = fmaxf(m_i[i], mx);
            float f    = __expf(m_i[i] - mnew);
            float sum  = 0.f;
            #pragma unroll
            for (int j = 0; j < 4; j++) { p[i][j] = __expf(sv[j] - mnew); sum += p[i][j]; }
            #pragma unroll
            for (int off = 1; off < 16; off <<= 1)
                sum += __shfl_xor_sync(0xffffffffu, sum, off);
            l_i[i] = l_i[i] * f + sum;
            m_i[i] = mnew;
            #pragma unroll
            for (int j = 0; j < 4; j++) acc[i][j] *= f;
        }

        __syncthreads();   // K reads of KPs done
        // store P transposed: KPs[kcol][qrow]
        #pragma unroll
        for (int j = 0; j < 4; j++) {
            float4 w = make_float4(p[0][j], p[1][j], p[2][j], p[3][j]);
            *(float4*)&KPs[4*tx + j][4*ty] = w;
        }
        __syncthreads();

        // acc += P V
        #pragma unroll 16
        for (int k = 0; k < 64; k++) {
            float4 a  = *(const float4*)&KPs[k][4*ty];
            float4 vv = *(const float4*)&Vs[k][4*tx];
            float av[4] = {a.x, a.y, a.z, a.w};
            float vw[4] = {vv.x, vv.y, vv.z, vv.w};
            #pragma unroll
            for (int i = 0; i < 4; i++)
                #pragma unroll
                for (int j = 0; j < 4; j++)
                    acc[i][j] = fmaf(av[i], vw[j], acc[i][j]);
        }
    }

    // normalize and write ctx[b, s, h, d]
    #pragma unroll
    for (int i = 0; i < 4; i++) {
        float inv = 1.0f / l_i[i];
        float4 o = make_float4(acc[i][0]*inv, acc[i][1]*inv, acc[i][2]*inv, acc[i][3]*inv);
        *(float4*)&g_ctx[(((size_t)b*S_ + q0 + 4*ty + i)*H_ + h)*D_ + 4*tx] = o;
    }
}

// ---------------------------------------------------------------------------
// Kernel C: output projection. out[m,n] = sum_k ctx[m,k]*Wo[k,n] + bo[n]
// grid: (BS/64, E/64), block 256
// ---------------------------------------------------------------------------
__global__ __launch_bounds__(256) void oproj_kernel(
    const float* __restrict__ Wo, const float* __restrict__ bo,
    float* __restrict__ out)
{
    __shared__ float Xs[16][64];
    __shared__ float Ws[16][64];

    const int m0  = blockIdx.x * 64;
    const int n0  = blockIdx.y * 64;
    const int tid = threadIdx.x;
    const int tx  = tid & 15, ty = tid >> 4;

    float acc[4][4] = {};

    const int lr  = tid >> 2;
    const int lc4 = (tid & 3) * 4;
    const int wd  = tid & 63;
    const int wk  = tid >> 6;

    const float* ctx = g_ctx;

    for (int e0 = 0; e0 < E_; e0 += 16) {
        __syncthreads();
        float4 xv = *(const float4*)&ctx[(size_t)(m0 + lr) * E_ + e0 + lc4];
        Xs[lc4 + 0][lr] = xv.x;
        Xs[lc4 + 1][lr] = xv.y;
        Xs[lc4 + 2][lr] = xv.z;
        Xs[lc4 + 3][lr] = xv.w;
        #pragma unroll
        for (int s = 0; s < 4; s++)
            Ws[wk + 4*s][wd] = Wo[(size_t)(e0 + wk + 4*s) * E_ + n0 + wd];
        __syncthreads();

        #pragma unroll
        for (int kk = 0; kk < 16; kk++) {
            float4 a = *(const float4*)&Xs[kk][4*ty];
            float4 b = *(const float4*)&Ws[kk][4*tx];
            float av[4] = {a.x, a.y, a.z, a.w};
            float bw[4] = {b.x, b.y, b.z, b.w};
            #pragma unroll
            for (int i = 0; i < 4; i++)
                #pragma unroll
                for (int j = 0; j < 4; j++)
                    acc[i][j] = fmaf(av[i], bw[j], acc[i][j]);
        }
    }

    #pragma unroll
    for (int i = 0; i < 4; i++) {
        int m = m0 + 4*ty + i;
        float4 o;
        o.x = acc[i][0] + bo[n0 + 4*tx + 0];
        o.y = acc[i][1] + bo[n0 + 4*tx + 1];
        o.z = acc[i][2] + bo[n0 + 4*tx + 2];
        o.w = acc[i][3] + bo[n0 + 4*tx + 3];
        *(float4*)&out[(size_t)m * E_ + n0 + 4*tx] = o;
    }
}

// ---------------------------------------------------------------------------
extern "C" void kernel_launch(void* const* d_in, const int* in_sizes, int n_in,
                              void* d_out, int out_size)
{
    const float* x    = (const float*)d_in[0];
    const int*   mask = (const int*)  d_in[1];
    const float* Wq   = (const float*)d_in[2];
    const float* bq   = (const float*)d_in[3];
    const float* Wk   = (const float*)d_in[4];
    const float* bk   = (const float*)d_in[5];
    const float* Wv   = (const float*)d_in[6];
    const float* bv   = (const float*)d_in[7];
    const float* Wo   = (const float*)d_in[8];
    const float* bo   = (const float*)d_in[9];
    float* out = (float*)d_out;

    dim3 gA(BS_/64, H_, 3);
    qkv_kernel<<<gA, 256>>>(x, Wq, bq, Wk, bk, Wv, bv);

    dim3 gB(S_/64, H_, B_);
    attn_kernel<<<gB, 256>>>(mask);

    dim3 gC(BS_/64, E_/64);
    oproj_kernel<<<gC, 256>>>(Wo, bo, out);
}

// round 5
// speedup vs baseline: 2.3473x; 2.3441x over previous
#include <cuda_runtime.h>
#include <cuda_bf16.h>

#define B_  2
#define S_  2048
#define E_  1024
#define H_  16
#define D_  64
#define BS_ (B_*S_)

// ---------------- split-bf16 device globals (no cudaMalloc allowed) --------
__device__ __nv_bfloat16 g_xh[(size_t)BS_*E_],  g_xl[(size_t)BS_*E_];     // x  [4096][1024]
__device__ __nv_bfloat16 g_wth[(size_t)3*H_*D_*E_], g_wtl[(size_t)3*H_*D_*E_]; // W^T [t][h][d][e]
__device__ __nv_bfloat16 g_woth[(size_t)E_*E_], g_wotl[(size_t)E_*E_];    // Wo^T [n][k]
__device__ __nv_bfloat16 g_qh[(size_t)B_*H_*S_*D_], g_ql[(size_t)B_*H_*S_*D_];
__device__ __nv_bfloat16 g_kh[(size_t)B_*H_*S_*D_], g_kl[(size_t)B_*H_*S_*D_];
__device__ __nv_bfloat16 g_vh[(size_t)B_*H_*S_*D_], g_vl[(size_t)B_*H_*S_*D_];
__device__ __nv_bfloat16 g_ch[(size_t)BS_*E_],  g_cl[(size_t)BS_*E_];     // ctx [4096][1024]

// ============================ helpers ======================================
__device__ __forceinline__ unsigned smem_u32(const void* p) {
    unsigned a;
    asm("{ .reg .u64 t; cvta.to.shared.u64 t, %1; cvt.u32.u64 %0, t; }"
        : "=r"(a) : "l"(p));
    return a;
}

__device__ __forceinline__ void ldsm4(unsigned r[4], unsigned addr) {
    asm volatile("ldmatrix.sync.aligned.m8n8.x4.shared.b16 {%0,%1,%2,%3}, [%4];"
        : "=r"(r[0]), "=r"(r[1]), "=r"(r[2]), "=r"(r[3]) : "r"(addr));
}
__device__ __forceinline__ void ldsm4t(unsigned r[4], unsigned addr) {
    asm volatile("ldmatrix.sync.aligned.m8n8.x4.trans.shared.b16 {%0,%1,%2,%3}, [%4];"
        : "=r"(r[0]), "=r"(r[1]), "=r"(r[2]), "=r"(r[3]) : "r"(addr));
}
__device__ __forceinline__ void mma_bf16(float c[4], const unsigned a[4],
                                         unsigned b0, unsigned b1) {
    asm volatile(
        "mma.sync.aligned.m16n8k16.row.col.f32.bf16.bf16.f32 "
        "{%0,%1,%2,%3}, {%4,%5,%6,%7}, {%8,%9}, {%0,%1,%2,%3};"
        : "+f"(c[0]), "+f"(c[1]), "+f"(c[2]), "+f"(c[3])
        : "r"(a[0]), "r"(a[1]), "r"(a[2]), "r"(a[3]), "r"(b0), "r"(b1));
}

__device__ __forceinline__ unsigned bf2u(float a, float b) {
    __nv_bfloat162 t = __floats2bfloat162_rn(a, b);
    return *(unsigned*)&t;
}
__device__ __forceinline__ void split_pair(float a, float b, unsigned& hi, unsigned& lo) {
    float ha = __bfloat162float(__float2bfloat16(a));
    float hb = __bfloat162float(__float2bfloat16(b));
    hi = bf2u(ha, hb);
    lo = bf2u(a - ha, b - hb);
}

// ============================ convert kernels ==============================
// x fp32 [4096][1024] -> g_xh/g_xl.  grid 4096, block 256, 4 elems/thread.
__global__ __launch_bounds__(256) void cvt_x_kernel(const float* __restrict__ x) {
    size_t i = (size_t)blockIdx.x * 256 + threadIdx.x;
    float4 v = ((const float4*)x)[i];
    unsigned h0, l0, h1, l1;
    split_pair(v.x, v.y, h0, l0);
    split_pair(v.z, v.w, h1, l1);
    ((uint2*)g_xh)[i] = make_uint2(h0, h1);
    ((uint2*)g_xl)[i] = make_uint2(l0, l1);
}

// Wq/Wk/Wv [h][e][d] fp32 -> g_wth/g_wtl [t][h][d][e].  grid 3072, 4 e/thread.
__global__ __launch_bounds__(256) void cvt_wqkv_kernel(
    const float* __restrict__ Wq, const float* __restrict__ Wk,
    const float* __restrict__ Wv) {
    size_t idx = ((size_t)blockIdx.x * 256 + threadIdx.x) * 4;
    int e = idx & 1023;
    int d = (idx >> 10) & 63;
    int h = (idx >> 16) & 15;
    int t = (int)(idx >> 20);
    const float* W = (t == 0) ? Wq : (t == 1) ? Wk : Wv;
    const float* src = W + ((size_t)h * E_ + e) * D_ + d;
    float v0 = src[0], v1 = src[D_], v2 = src[2*D_], v3 = src[3*D_];
    unsigned h0, l0, h1, l1;
    split_pair(v0, v1, h0, l0);
    split_pair(v2, v3, h1, l1);
    *(uint2*)(g_wth + idx) = make_uint2(h0, h1);
    *(uint2*)(g_wtl + idx) = make_uint2(l0, l1);
}

// Wo [k][n] fp32 -> g_woth/g_wotl [n][k].  grid 1024, 4 k/thread.
__global__ __launch_bounds__(256) void cvt_wo_kernel(const float* __restrict__ Wo) {
    size_t idx = ((size_t)blockIdx.x * 256 + threadIdx.x) * 4;
    int k = idx & 1023;
    int n = (int)(idx >> 10);
    float v0 = Wo[(size_t)(k+0)*E_ + n];
    float v1 = Wo[(size_t)(k+1)*E_ + n];
    float v2 = Wo[(size_t)(k+2)*E_ + n];
    float v3 = Wo[(size_t)(k+3)*E_ + n];
    unsigned h0, l0, h1, l1;
    split_pair(v0, v1, h0, l0);
    split_pair(v2, v3, h1, l1);
    *(uint2*)(g_woth + idx) = make_uint2(h0, h1);
    *(uint2*)(g_wotl + idx) = make_uint2(l0, l1);
}

// ============================ GEMM core ====================================
// C[128,64] = A[128,1024] * B[64,1024]^T with split-bf16 3-term MMA.
// A, B pre-split bf16 globals with K contiguous (stride 1024).
// Block 256 = 8 warps, warp grid 4(M)x2(N), each warp 32x32.
#define GS 40   // smem row stride (bf16 elems): conflict-free for ldmatrix

__device__ __forceinline__ void gemm_core(
    const __nv_bfloat16* __restrict__ Agh, const __nv_bfloat16* __restrict__ Agl,
    const __nv_bfloat16* __restrict__ Bgh, const __nv_bfloat16* __restrict__ Bgl,
    __nv_bfloat16* sAh, __nv_bfloat16* sAl,
    __nv_bfloat16* sBh, __nv_bfloat16* sBl,
    float acc[2][4][4])
{
    const int tid = threadIdx.x, lane = tid & 31, wid = tid >> 5;
    const int m_off = (wid >> 1) * 32, n_off = (wid & 1) * 32;
    const int lrow = lane & 15, lcol = (lane >> 4) << 3;
    const unsigned saAh = smem_u32(sAh), saAl = smem_u32(sAl);
    const unsigned saBh = smem_u32(sBh), saBl = smem_u32(sBl);

    const int a_r = tid >> 2;            // 0..63
    const int a_k = (tid & 3) * 8;       // 0,8,16,24

    for (int c = 0; c < 32; c++) {
        __syncthreads();
        // A tile copy: rows a_r and a_r+64
        {
            size_t o0 = (size_t)a_r * E_ + c * 32 + a_k;
            size_t o1 = (size_t)(a_r + 64) * E_ + c * 32 + a_k;
            *(uint4*)(sAh + a_r * GS + a_k)        = *(const uint4*)(Agh + o0);
            *(uint4*)(sAl + a_r * GS + a_k)        = *(const uint4*)(Agl + o0);
            *(uint4*)(sAh + (a_r + 64) * GS + a_k) = *(const uint4*)(Agh + o1);
            *(uint4*)(sAl + (a_r + 64) * GS + a_k) = *(const uint4*)(Agl + o1);
        }
        // B tile copy: row a_r (=n), cols a_k
        {
            size_t o = (size_t)a_r * E_ + c * 32 + a_k;
            *(uint4*)(sBh + a_r * GS + a_k) = *(const uint4*)(Bgh + o);
            *(uint4*)(sBl + a_r * GS + a_k) = *(const uint4*)(Bgl + o);
        }
        __syncthreads();

        #pragma unroll
        for (int kk = 0; kk < 32; kk += 16) {
            unsigned ah[2][4], al[2][4], bh[2][4], bl[2][4];
            #pragma unroll
            for (int mf = 0; mf < 2; mf++) {
                unsigned off = (unsigned)(((m_off + mf*16 + lrow) * GS + kk + lcol) * 2);
                ldsm4(ah[mf], saAh + off);
                ldsm4(al[mf], saAl + off);
            }
            #pragma unroll
            for (int g = 0; g < 2; g++) {
                unsigned off = (unsigned)(((n_off + g*16 + lrow) * GS + kk + lcol) * 2);
                ldsm4(bh[g], saBh + off);
                ldsm4(bl[g], saBl + off);
            }
            #pragma unroll
            for (int mf = 0; mf < 2; mf++)
                #pragma unroll
                for (int nf = 0; nf < 4; nf++) {
                    unsigned b0h = bh[nf>>1][nf&1], b1h = bh[nf>>1][2+(nf&1)];
                    unsigned b0l = bl[nf>>1][nf&1], b1l = bl[nf>>1][2+(nf&1)];
                    mma_bf16(acc[mf][nf], ah[mf], b0h, b1h);
                    mma_bf16(acc[mf][nf], ah[mf], b0l, b1l);
                    mma_bf16(acc[mf][nf], al[mf], b0h, b1h);
                }
        }
    }
}

// ---------------------------------------------------------------------------
// QKV: grid (32, 16, 3), block 256. Writes split-bf16 q/k/v [b][h][s][d].
// ---------------------------------------------------------------------------
__global__ __launch_bounds__(256) void qkv_mma_kernel(
    const float* __restrict__ bq, const float* __restrict__ bk,
    const float* __restrict__ bv)
{
    __shared__ __nv_bfloat16 sAh[128*GS], sAl[128*GS], sBh[64*GS], sBl[64*GS];

    const int m0 = blockIdx.x * 128, h = blockIdx.y, t = blockIdx.z;
    const int lane = threadIdx.x & 31, wid = threadIdx.x >> 5;
    const int m_off = (wid >> 1) * 32, n_off = (wid & 1) * 32;
    const int r = lane >> 2, c2 = (lane & 3) * 2;

    const __nv_bfloat16* Bgh = g_wth + (size_t)(t * H_ + h) * D_ * E_;
    const __nv_bfloat16* Bgl = g_wtl + (size_t)(t * H_ + h) * D_ * E_;
    const float* bias = ((t == 0) ? bq : (t == 1) ? bk : bv) + h * D_;
    __nv_bfloat16* oh = (t == 0) ? g_qh : (t == 1) ? g_kh : g_vh;
    __nv_bfloat16* ol = (t == 0) ? g_ql : (t == 1) ? g_kl : g_vl;

    float acc[2][4][4] = {};
    gemm_core(g_xh + (size_t)m0 * E_, g_xl + (size_t)m0 * E_,
              Bgh, Bgl, sAh, sAl, sBh, sBl, acc);

    #pragma unroll
    for (int mf = 0; mf < 2; mf++)
        #pragma unroll
        for (int nf = 0; nf < 4; nf++) {
            int col = n_off + nf*8 + c2;
            float b0 = bias[col], b1 = bias[col+1];
            #pragma unroll
            for (int half = 0; half < 2; half++) {
                int m = m0 + m_off + mf*16 + r + half*8;
                int bb = m >> 11, sl = m & (S_-1);
                size_t idx = (((size_t)bb*H_ + h)*S_ + sl)*D_ + col;
                unsigned hi, lo;
                split_pair(acc[mf][nf][2*half] + b0, acc[mf][nf][2*half+1] + b1, hi, lo);
                *(unsigned*)(oh + idx) = hi;
                *(unsigned*)(ol + idx) = lo;
            }
        }
}

// ---------------------------------------------------------------------------
// Output projection: grid (32, 16), block 256. fp32 out.
// ---------------------------------------------------------------------------
__global__ __launch_bounds__(256) void oproj_mma_kernel(
    const float* __restrict__ bo, float* __restrict__ out)
{
    __shared__ __nv_bfloat16 sAh[128*GS], sAl[128*GS], sBh[64*GS], sBl[64*GS];

    const int m0 = blockIdx.x * 128, n0 = blockIdx.y * 64;
    const int lane = threadIdx.x & 31, wid = threadIdx.x >> 5;
    const int m_off = (wid >> 1) * 32, n_off = (wid & 1) * 32;
    const int r = lane >> 2, c2 = (lane & 3) * 2;

    float acc[2][4][4] = {};
    gemm_core(g_ch + (size_t)m0 * E_, g_cl + (size_t)m0 * E_,
              g_woth + (size_t)n0 * E_, g_wotl + (size_t)n0 * E_,
              sAh, sAl, sBh, sBl, acc);

    #pragma unroll
    for (int mf = 0; mf < 2; mf++)
        #pragma unroll
        for (int nf = 0; nf < 4; nf++) {
            int col = n_off + nf*8 + c2;
            float b0 = bo[n0+col], b1 = bo[n0+col+1];
            #pragma unroll
            for (int half = 0; half < 2; half++) {
                int m = m0 + m_off + mf*16 + r + half*8;
                float2 v = make_float2(acc[mf][nf][2*half] + b0,
                                       acc[mf][nf][2*half+1] + b1);
                *(float2*)(out + (size_t)m*E_ + n0 + col) = v;
            }
        }
}

// ---------------------------------------------------------------------------
// Flash attention with HMMA. grid (32, 16, 2), block 256 (8 warps: 4m x 2n).
// Dynamic smem 56320B: P/Q,K,V split tiles [64][72] + reduction arrays.
// ---------------------------------------------------------------------------
#define AS 72   // attention smem row stride (bf16 elems)

__global__ __launch_bounds__(256) void attn_mma_kernel(const int* __restrict__ mask)
{
    extern __shared__ char dsm[];
    __nv_bfloat16* Ph = (__nv_bfloat16*)dsm;        // Q first, later P
    __nv_bfloat16* Pl = Ph + 64*AS;
    __nv_bfloat16* Kh = Pl + 64*AS;
    __nv_bfloat16* Kl = Kh + 64*AS;
    __nv_bfloat16* Vh = Kl + 64*AS;
    __nv_bfloat16* Vl = Vh + 64*AS;
    float* red_mx = (float*)(Vl + 64*AS);           // [4 m_w][2 n_w][16 rows]
    float* red_sm = red_mx + 128;

    const int q0 = blockIdx.x * 64, h = blockIdx.y, b = blockIdx.z;
    const int tid = threadIdx.x, lane = tid & 31, wid = tid >> 5;
    const int m_w = wid >> 1, n_w = wid & 1;
    const int m_off = m_w * 16, n_off = n_w * 32;
    const int r = lane >> 2, c2 = (lane & 3) * 2;
    const int lrow = lane & 15, lcol = (lane >> 4) << 3;

    const size_t base = ((size_t)b*H_ + h) * S_ * D_;
    const __nv_bfloat16 *Qh = g_qh + base, *Ql = g_ql + base;
    const __nv_bfloat16 *Kgh = g_kh + base, *Kgl = g_kl + base;
    const __nv_bfloat16 *Vgh = g_vh + base, *Vgl = g_vl + base;
    const int* Mb = mask + (size_t)b * S_ * S_;

    const unsigned sPh = smem_u32(Ph), sPl = smem_u32(Pl);
    const unsigned sKh = smem_u32(Kh), sKl = smem_u32(Kl);
    const unsigned sVh = smem_u32(Vh), sVl = smem_u32(Vl);

    // copy indices for 64x64 bf16 tiles: 2 uint4 per thread per buffer
    const int t_r0 = tid >> 3;            // 0..31
    const int t_d  = (tid & 7) * 8;       // 0..56

    // ---- load Q tile into (P) buffer, pull A-fragments into registers ----
    {
        size_t o0 = (size_t)(q0 + t_r0) * D_ + t_d;
        size_t o1 = (size_t)(q0 + t_r0 + 32) * D_ + t_d;
        *(uint4*)(Ph + t_r0*AS + t_d)      = *(const uint4*)(Qh + o0);
        *(uint4*)(Pl + t_r0*AS + t_d)      = *(const uint4*)(Ql + o0);
        *(uint4*)(Ph + (t_r0+32)*AS + t_d) = *(const uint4*)(Qh + o1);
        *(uint4*)(Pl + (t_r0+32)*AS + t_d) = *(const uint4*)(Ql + o1);
    }
    __syncthreads();
    unsigned qh[4][4], ql[4][4];
    #pragma unroll
    for (int ks = 0; ks < 4; ks++) {
        unsigned off = (unsigned)(((m_off + lrow)*AS + ks*16 + lcol) * 2);
        ldsm4(qh[ks], sPh + off);
        ldsm4(ql[ks], sPl + off);
    }
    __syncthreads();

    float o[4][4] = {};
    float mi0 = -1e30f, mi1 = -1e30f, li0 = 0.f, li1 = 0.f;

    for (int k0 = 0; k0 < S_; k0 += 64) {
        __syncthreads();   // prior chunk's P/V reads done before overwrite
        // ---- K, V tile copies ----
        {
            size_t o0 = (size_t)(k0 + t_r0) * D_ + t_d;
            size_t o1 = (size_t)(k0 + t_r0 + 32) * D_ + t_d;
            *(uint4*)(Kh + t_r0*AS + t_d)      = *(const uint4*)(Kgh + o0);
            *(uint4*)(Kl + t_r0*AS + t_d)      = *(const uint4*)(Kgl + o0);
            *(uint4*)(Kh + (t_r0+32)*AS + t_d) = *(const uint4*)(Kgh + o1);
            *(uint4*)(Kl + (t_r0+32)*AS + t_d) = *(const uint4*)(Kgl + o1);
            *(uint4*)(Vh + t_r0*AS + t_d)      = *(const uint4*)(Vgh + o0);
            *(uint4*)(Vl + t_r0*AS + t_d)      = *(const uint4*)(Vgl + o0);
            *(uint4*)(Vh + (t_r0+32)*AS + t_d) = *(const uint4*)(Vgh + o1);
            *(uint4*)(Vl + (t_r0+32)*AS + t_d) = *(const uint4*)(Vgl + o1);
        }
        __syncthreads();

        // ---- S = Q K^T (warp: 16 q x 32 keys) ----
        float s[4][4] = {};
        #pragma unroll
        for (int ks = 0; ks < 4; ks++) {
            unsigned bh[2][4], bl[2][4];
            #pragma unroll
            for (int g = 0; g < 2; g++) {
                unsigned off = (unsigned)(((n_off + g*16 + lrow)*AS + ks*16 + lcol) * 2);
                ldsm4(bh[g], sKh + off);
                ldsm4(bl[g], sKl + off);
            }
            #pragma unroll
            for (int nf = 0; nf < 4; nf++) {
                unsigned b0h = bh[nf>>1][nf&1], b1h = bh[nf>>1][2+(nf&1)];
                unsigned b0l = bl[nf>>1][nf&1], b1l = bl[nf>>1][2+(nf&1)];
                mma_bf16(s[nf], qh[ks], b0h, b1h);
                mma_bf16(s[nf], qh[ks], b0l, b1l);
                mma_bf16(s[nf], ql[ks], b0h, b1h);
            }
        }

        // ---- mask + scale + row max ----
        const int row0g = q0 + m_off + r;
        float mx0 = -1e30f, mx1 = -1e30f;
        #pragma unroll
        for (int nf = 0; nf < 4; nf++) {
            int colg = k0 + n_off + nf*8 + c2;
            int2 mv0 = *(const int2*)(Mb + (size_t)row0g*S_ + colg);
            int2 mv1 = *(const int2*)(Mb + (size_t)(row0g+8)*S_ + colg);
            s[nf][0] = mv0.x ? s[nf][0]*0.125f : -1e9f;
            s[nf][1] = mv0.y ? s[nf][1]*0.125f : -1e9f;
            s[nf][2] = mv1.x ? s[nf][2]*0.125f : -1e9f;
            s[nf][3] = mv1.y ? s[nf][3]*0.125f : -1e9f;
            mx0 = fmaxf(mx0, fmaxf(s[nf][0], s[nf][1]));
            mx1 = fmaxf(mx1, fmaxf(s[nf][2], s[nf][3]));
        }
        mx0 = fmaxf(mx0, __shfl_xor_sync(0xffffffffu, mx0, 1));
        mx0 = fmaxf(mx0, __shfl_xor_sync(0xffffffffu, mx0, 2));
        mx1 = fmaxf(mx1, __shfl_xor_sync(0xffffffffu, mx1, 1));
        mx1 = fmaxf(mx1, __shfl_xor_sync(0xffffffffu, mx1, 2));
        if ((lane & 3) == 0) {
            red_mx[m_w*32 + n_w*16 + r]     = mx0;
            red_mx[m_w*32 + n_w*16 + r + 8] = mx1;
        }
        __syncthreads();
        float cm0 = fmaxf(red_mx[m_w*32 + r],     red_mx[m_w*32 + 16 + r]);
        float cm1 = fmaxf(red_mx[m_w*32 + r + 8], red_mx[m_w*32 + 24 + r]);

        float mn0 = fmaxf(mi0, cm0), mn1 = fmaxf(mi1, cm1);
        float f0 = __expf(mi0 - mn0), f1 = __expf(mi1 - mn1);
        mi0 = mn0; mi1 = mn1;

        // ---- exp, partial sums, store split P to smem ----
        float sm0 = 0.f, sm1 = 0.f;
        #pragma unroll
        for (int nf = 0; nf < 4; nf++) {
            float p0 = __expf(s[nf][0] - mn0), p1 = __expf(s[nf][1] - mn0);
            float p2 = __expf(s[nf][2] - mn1), p3 = __expf(s[nf][3] - mn1);
            sm0 += p0 + p1; sm1 += p2 + p3;
            int col = n_off + nf*8 + c2;
            unsigned hi, lo;
            split_pair(p0, p1, hi, lo);
            *(unsigned*)(Ph + (m_off + r)*AS + col) = hi;
            *(unsigned*)(Pl + (m_off + r)*AS + col) = lo;
            split_pair(p2, p3, hi, lo);
            *(unsigned*)(Ph + (m_off + r + 8)*AS + col) = hi;
            *(unsigned*)(Pl + (m_off + r + 8)*AS + col) = lo;
        }
        sm0 += __shfl_xor_sync(0xffffffffu, sm0, 1);
        sm0 += __shfl_xor_sync(0xffffffffu, sm0, 2);
        sm1 += __shfl_xor_sync(0xffffffffu, sm1, 1);
        sm1 += __shfl_xor_sync(0xffffffffu, sm1, 2);
        if ((lane & 3) == 0) {
            red_sm[m_w*32 + n_w*16 + r]     = sm0;
            red_sm[m_w*32 + n_w*16 + r + 8] = sm1;
        }
        __syncthreads();   // also publishes P for the PV mma
        li0 = li0*f0 + red_sm[m_w*32 + r]     + red_sm[m_w*32 + 16 + r];
        li1 = li1*f1 + red_sm[m_w*32 + r + 8] + red_sm[m_w*32 + 24 + r];

        #pragma unroll
        for (int df = 0; df < 4; df++) {
            o[df][0] *= f0; o[df][1] *= f0;
            o[df][2] *= f1; o[df][3] *= f1;
        }

        // ---- O += P V (warp: 16 q x 32 d; n_off reused as d offset) ----
        #pragma unroll
        for (int ks = 0; ks < 4; ks++) {
            unsigned ph4[4], pl4[4];
            unsigned aoff = (unsigned)(((m_off + lrow)*AS + ks*16 + lcol) * 2);
            ldsm4(ph4, sPh + aoff);
            ldsm4(pl4, sPl + aoff);
            unsigned vh[2][4], vl[2][4];
            #pragma unroll
            for (int g = 0; g < 2; g++) {
                unsigned boff = (unsigned)(((ks*16 + lrow)*AS + n_off + g*16 + lcol) * 2);
                ldsm4t(vh[g], sVh + boff);
                ldsm4t(vl[g], sVl + boff);
            }
            #pragma unroll
            for (int df = 0; df < 4; df++) {
                unsigned b0h = vh[df>>1][(df&1)*2], b1h = vh[df>>1][(df&1)*2 + 1];
                unsigned b0l = vl[df>>1][(df&1)*2], b1l = vl[df>>1][(df&1)*2 + 1];
                mma_bf16(o[df], ph4, b0h, b1h);
                mma_bf16(o[df], ph4, b0l, b1l);
                mma_bf16(o[df], pl4, b0h, b1h);
            }
        }
    }

    // ---- normalize & write split ctx [b][s][h*64+d] ----
    float inv0 = 1.f / li0, inv1 = 1.f / li1;
    int rowg0 = q0 + m_off + r;
    #pragma unroll
    for (int df = 0; df < 4; df++) {
        int col = n_off + df*8 + c2;
        size_t i0 = ((size_t)(b*S_ + rowg0))*E_ + h*D_ + col;
        size_t i1 = ((size_t)(b*S_ + rowg0 + 8))*E_ + h*D_ + col;
        unsigned hi, lo;
        split_pair(o[df][0]*inv0, o[df][1]*inv0, hi, lo);
        *(unsigned*)(g_ch + i0) = hi;
        *(unsigned*)(g_cl + i0) = lo;
        split_pair(o[df][2]*inv1, o[df][3]*inv1, hi, lo);
        *(unsigned*)(g_ch + i1) = hi;
        *(unsigned*)(g_cl + i1) = lo;
    }
}

#define ATTN_SMEM (6*64*AS*2 + 256*4)   // 55296 + 1024 = 56320

// ---------------------------------------------------------------------------
extern "C" void kernel_launch(void* const* d_in, const int* in_sizes, int n_in,
                              void* d_out, int out_size)
{
    const float* x    = (const float*)d_in[0];
    const int*   mask = (const int*)  d_in[1];
    const float* Wq   = (const float*)d_in[2];
    const float* bq   = (const float*)d_in[3];
    const float* Wk   = (const float*)d_in[4];
    const float* bk   = (const float*)d_in[5];
    const float* Wv   = (const float*)d_in[6];
    const float* bv   = (const float*)d_in[7];
    const float* Wo   = (const float*)d_in[8];
    const float* bo   = (const float*)d_in[9];
    float* out = (float*)d_out;

    cudaFuncSetAttribute(attn_mma_kernel,
        cudaFuncAttributeMaxDynamicSharedMemorySize, ATTN_SMEM);

    cvt_x_kernel   <<<BS_*E_/4/256, 256>>>(x);
    cvt_wqkv_kernel<<<3*H_*D_*E_/4/256, 256>>>(Wq, Wk, Wv);
    cvt_wo_kernel  <<<E_*E_/4/256, 256>>>(Wo);

    dim3 gA(BS_/128, H_, 3);
    qkv_mma_kernel<<<gA, 256>>>(bq, bk, bv);

    dim3 gB(S_/64, H_, B_);
    attn_mma_kernel<<<gB, 256, ATTN_SMEM>>>(mask);

    dim3 gC(BS_/128, E_/64);
    oproj_mma_kernel<<<gC, 256>>>(bo, out);
}

// round 6
// speedup vs baseline: 2.4904x; 1.0609x over previous
#include <cuda_runtime.h>
#include <cuda_bf16.h>

#define B_  2
#define S_  2048
#define E_  1024
#define H_  16
#define D_  64
#define BS_ (B_*S_)

// ---------------- split-bf16 device globals (no cudaMalloc allowed) --------
__device__ __nv_bfloat16 g_xh[(size_t)BS_*E_],  g_xl[(size_t)BS_*E_];     // x  [4096][1024]
__device__ __nv_bfloat16 g_wth[(size_t)3*H_*D_*E_], g_wtl[(size_t)3*H_*D_*E_]; // W^T [t][h][d][e] = [3072][1024]
__device__ __nv_bfloat16 g_woth[(size_t)E_*E_], g_wotl[(size_t)E_*E_];    // Wo^T [n][k]
__device__ __nv_bfloat16 g_qh[(size_t)B_*H_*S_*D_], g_ql[(size_t)B_*H_*S_*D_];
__device__ __nv_bfloat16 g_kh[(size_t)B_*H_*S_*D_], g_kl[(size_t)B_*H_*S_*D_];
__device__ __nv_bfloat16 g_vh[(size_t)B_*H_*S_*D_], g_vl[(size_t)B_*H_*S_*D_];
__device__ __nv_bfloat16 g_ch[(size_t)BS_*E_],  g_cl[(size_t)BS_*E_];     // ctx [4096][1024]

// ============================ helpers ======================================
__device__ __forceinline__ unsigned smem_u32(const void* p) {
    unsigned a;
    asm("{ .reg .u64 t; cvta.to.shared.u64 t, %1; cvt.u32.u64 %0, t; }"
        : "=r"(a) : "l"(p));
    return a;
}

__device__ __forceinline__ void ldsm4(unsigned r[4], unsigned addr) {
    asm volatile("ldmatrix.sync.aligned.m8n8.x4.shared.b16 {%0,%1,%2,%3}, [%4];"
        : "=r"(r[0]), "=r"(r[1]), "=r"(r[2]), "=r"(r[3]) : "r"(addr));
}
__device__ __forceinline__ void ldsm4t(unsigned r[4], unsigned addr) {
    asm volatile("ldmatrix.sync.aligned.m8n8.x4.trans.shared.b16 {%0,%1,%2,%3}, [%4];"
        : "=r"(r[0]), "=r"(r[1]), "=r"(r[2]), "=r"(r[3]) : "r"(addr));
}
__device__ __forceinline__ void mma_bf16(float c[4], const unsigned a[4],
                                         unsigned b0, unsigned b1) {
    asm volatile(
        "mma.sync.aligned.m16n8k16.row.col.f32.bf16.bf16.f32 "
        "{%0,%1,%2,%3}, {%4,%5,%6,%7}, {%8,%9}, {%0,%1,%2,%3};"
        : "+f"(c[0]), "+f"(c[1]), "+f"(c[2]), "+f"(c[3])
        : "r"(a[0]), "r"(a[1]), "r"(a[2]), "r"(a[3]), "r"(b0), "r"(b1));
}

__device__ __forceinline__ unsigned bf2u(float a, float b) {
    __nv_bfloat162 t = __floats2bfloat162_rn(a, b);
    return *(unsigned*)&t;
}
__device__ __forceinline__ void split_pair(float a, float b, unsigned& hi, unsigned& lo) {
    float ha = __bfloat162float(__float2bfloat16(a));
    float hb = __bfloat162float(__float2bfloat16(b));
    hi = bf2u(ha, hb);
    lo = bf2u(a - ha, b - hb);
}

__device__ __forceinline__ void cpa16(unsigned dst, const void* src) {
    asm volatile("cp.async.cg.shared.global [%0], [%1], 16;"
        :: "r"(dst), "l"(__cvta_generic_to_global(src)) : "memory");
}
#define CP_COMMIT() asm volatile("cp.async.commit_group;" ::: "memory")
#define CP_WAIT0()  asm volatile("cp.async.wait_group 0;" ::: "memory")

// ============================ convert kernels ==============================
__global__ __launch_bounds__(256) void cvt_x_kernel(const float* __restrict__ x) {
    size_t i = (size_t)blockIdx.x * 256 + threadIdx.x;
    float4 v = ((const float4*)x)[i];
    unsigned h0, l0, h1, l1;
    split_pair(v.x, v.y, h0, l0);
    split_pair(v.z, v.w, h1, l1);
    ((uint2*)g_xh)[i] = make_uint2(h0, h1);
    ((uint2*)g_xl)[i] = make_uint2(l0, l1);
}

__global__ __launch_bounds__(256) void cvt_wqkv_kernel(
    const float* __restrict__ Wq, const float* __restrict__ Wk,
    const float* __restrict__ Wv) {
    size_t idx = ((size_t)blockIdx.x * 256 + threadIdx.x) * 4;
    int e = idx & 1023;
    int d = (idx >> 10) & 63;
    int h = (idx >> 16) & 15;
    int t = (int)(idx >> 20);
    const float* W = (t == 0) ? Wq : (t == 1) ? Wk : Wv;
    const float* src = W + ((size_t)h * E_ + e) * D_ + d;
    float v0 = src[0], v1 = src[D_], v2 = src[2*D_], v3 = src[3*D_];
    unsigned h0, l0, h1, l1;
    split_pair(v0, v1, h0, l0);
    split_pair(v2, v3, h1, l1);
    *(uint2*)(g_wth + idx) = make_uint2(h0, h1);
    *(uint2*)(g_wtl + idx) = make_uint2(l0, l1);
}

__global__ __launch_bounds__(256) void cvt_wo_kernel(const float* __restrict__ Wo) {
    size_t idx = ((size_t)blockIdx.x * 256 + threadIdx.x) * 4;
    int k = idx & 1023;
    int n = (int)(idx >> 10);
    float v0 = Wo[(size_t)(k+0)*E_ + n];
    float v1 = Wo[(size_t)(k+1)*E_ + n];
    float v2 = Wo[(size_t)(k+2)*E_ + n];
    float v3 = Wo[(size_t)(k+3)*E_ + n];
    unsigned h0, l0, h1, l1;
    split_pair(v0, v1, h0, l0);
    split_pair(v2, v3, h1, l1);
    *(uint2*)(g_woth + idx) = make_uint2(h0, h1);
    *(uint2*)(g_wotl + idx) = make_uint2(l0, l1);
}

// ============================ fused GEMM core ==============================
// C[128,128] CTA tile of C = A[M,1024] * B[N,1024]^T, split-bf16 3-term.
// 8 warps (4m x 2n), warp tile 32x64. cp.async 2-stage double buffer, k-chunk 32.
#define GS 40                     // smem row stride (bf16): ldmatrix conflict-free
#define STAGE_E  (128*GS)         // elems per buffer
#define BUF_B    (STAGE_E*2)      // bytes per buffer (10240)
#define STAGE_B  (BUF_B*4)        // bytes per stage  (40960)
#define GEMM_SMEM (STAGE_B*2)     // 81920

__device__ __forceinline__ void gemm_load_stage(
    unsigned sb, int st, int c,
    const __nv_bfloat16* Agh, const __nv_bfloat16* Agl,
    const __nv_bfloat16* Bgh, const __nv_bfloat16* Bgl)
{
    const int tid = threadIdx.x;
    unsigned base = sb + st * STAGE_B;
    #pragma unroll
    for (int u = 0; u < 2; u++) {
        int slot = tid + u * 256;
        int row = slot >> 2;
        int kq  = (slot & 3) * 8;
        unsigned doff = (unsigned)(row * GS + kq) * 2;
        size_t g = (size_t)row * E_ + c * 32 + kq;
        cpa16(base + doff,             Agh + g);
        cpa16(base + BUF_B + doff,     Agl + g);
        cpa16(base + 2*BUF_B + doff,   Bgh + g);
        cpa16(base + 3*BUF_B + doff,   Bgl + g);
    }
}

__device__ __forceinline__ void gemm_core2(
    const __nv_bfloat16* __restrict__ Agh, const __nv_bfloat16* __restrict__ Agl,
    const __nv_bfloat16* __restrict__ Bgh, const __nv_bfloat16* __restrict__ Bgl,
    unsigned sb, float acc[2][8][4])
{
    const int lane = threadIdx.x & 31, wid = threadIdx.x >> 5;
    const int m_off = (wid >> 1) * 32, n_off = (wid & 1) * 64;
    const int lrow = lane & 15, lcol = (lane >> 4) << 3;

    gemm_load_stage(sb, 0, 0, Agh, Agl, Bgh, Bgl);
    CP_COMMIT();

    for (int c = 0; c < 32; c++) {
        CP_WAIT0();
        __syncthreads();
        if (c < 31) {
            gemm_load_stage(sb, (c + 1) & 1, c + 1, Agh, Agl, Bgh, Bgl);
            CP_COMMIT();
        }
        unsigned As  = sb + (c & 1) * STAGE_B;
        unsigned Ahb = As, Alb = As + BUF_B, Bhb = As + 2*BUF_B, Blb = As + 3*BUF_B;

        #pragma unroll
        for (int kk = 0; kk < 32; kk += 16) {
            unsigned ah[2][4], al[2][4];
            #pragma unroll
            for (int mf = 0; mf < 2; mf++) {
                unsigned off = (unsigned)(((m_off + mf*16 + lrow) * GS + kk + lcol) * 2);
                ldsm4(ah[mf], Ahb + off);
                ldsm4(al[mf], Alb + off);
            }
            #pragma unroll
            for (int g = 0; g < 4; g++) {
                unsigned bh4[4], bl4[4];
                unsigned boff = (unsigned)(((n_off + g*16 + lrow) * GS + kk + lcol) * 2);
                ldsm4(bh4, Bhb + boff);
                ldsm4(bl4, Blb + boff);
                #pragma unroll
                for (int mf = 0; mf < 2; mf++)
                    #pragma unroll
                    for (int p = 0; p < 2; p++) {
                        int nf = g*2 + p;
                        mma_bf16(acc[mf][nf], ah[mf], bh4[p], bh4[2+p]);
                        mma_bf16(acc[mf][nf], ah[mf], bl4[p], bl4[2+p]);
                        mma_bf16(acc[mf][nf], al[mf], bh4[p], bh4[2+p]);
                    }
            }
        }
    }
}

// ---------------------------------------------------------------------------
// Fused QKV: C[4096,3072] = X * WT^T.  grid (32, 24), block 256.
// Epilogue: split-bf16 q/k/v in [b][h][s][d] + bias.
// ---------------------------------------------------------------------------
__global__ __launch_bounds__(256) void qkv_fused_kernel(
    const float* __restrict__ bq, const float* __restrict__ bk,
    const float* __restrict__ bv)
{
    extern __shared__ char dsm[];
    unsigned sb = smem_u32(dsm);

    const int m0 = blockIdx.x * 128, n0 = blockIdx.y * 128;
    const int lane = threadIdx.x & 31, wid = threadIdx.x >> 5;
    const int m_off = (wid >> 1) * 32, n_off = (wid & 1) * 64;
    const int r = lane >> 2, c2 = (lane & 3) * 2;

    float acc[2][8][4] = {};
    gemm_core2(g_xh + (size_t)m0 * E_, g_xl + (size_t)m0 * E_,
               g_wth + (size_t)n0 * E_, g_wtl + (size_t)n0 * E_, sb, acc);

    const int ng0 = n0 + n_off;              // 64-aligned: one (t,h) per warp
    const int t = ng0 >> 10;
    const int h = (ng0 >> 6) & 15;
    const float* bias = ((t == 0) ? bq : (t == 1) ? bk : bv) + h * D_;
    __nv_bfloat16* oh = (t == 0) ? g_qh : (t == 1) ? g_kh : g_vh;
    __nv_bfloat16* ol = (t == 0) ? g_ql : (t == 1) ? g_kl : g_vl;

    #pragma unroll
    for (int mf = 0; mf < 2; mf++)
        #pragma unroll
        for (int nf = 0; nf < 8; nf++) {
            int d = nf*8 + c2;
            float b0 = bias[d], b1 = bias[d+1];
            #pragma unroll
            for (int half = 0; half < 2; half++) {
                int m = m0 + m_off + mf*16 + r + half*8;
                int bb = m >> 11, sl = m & (S_-1);
                size_t idx = (((size_t)bb*H_ + h)*S_ + sl)*D_ + d;
                unsigned hi, lo;
                split_pair(acc[mf][nf][2*half] + b0, acc[mf][nf][2*half+1] + b1, hi, lo);
                *(unsigned*)(oh + idx) = hi;
                *(unsigned*)(ol + idx) = lo;
            }
        }
}

// ---------------------------------------------------------------------------
// Output projection: C[4096,1024] = ctx * WoT^T.  grid (32, 8), block 256.
// ---------------------------------------------------------------------------
__global__ __launch_bounds__(256) void oproj_fused_kernel(
    const float* __restrict__ bo, float* __restrict__ out)
{
    extern __shared__ char dsm[];
    unsigned sb = smem_u32(dsm);

    const int m0 = blockIdx.x * 128, n0 = blockIdx.y * 128;
    const int lane = threadIdx.x & 31, wid = threadIdx.x >> 5;
    const int m_off = (wid >> 1) * 32, n_off = (wid & 1) * 64;
    const int r = lane >> 2, c2 = (lane & 3) * 2;

    float acc[2][8][4] = {};
    gemm_core2(g_ch + (size_t)m0 * E_, g_cl + (size_t)m0 * E_,
               g_woth + (size_t)n0 * E_, g_wotl + (size_t)n0 * E_, sb, acc);

    #pragma unroll
    for (int mf = 0; mf < 2; mf++)
        #pragma unroll
        for (int nf = 0; nf < 8; nf++) {
            int col = n0 + n_off + nf*8 + c2;
            float b0 = bo[col], b1 = bo[col+1];
            #pragma unroll
            for (int half = 0; half < 2; half++) {
                int m = m0 + m_off + mf*16 + r + half*8;
                float2 v = make_float2(acc[mf][nf][2*half] + b0,
                                       acc[mf][nf][2*half+1] + b1);
                *(float2*)(out + (size_t)m*E_ + col) = v;
            }
        }
}

// ---------------------------------------------------------------------------
// Flash attention with HMMA (unchanged from round 5).
// grid (32, 16, 2), block 256 (8 warps: 4m x 2n).
// ---------------------------------------------------------------------------
#define AS 72   // attention smem row stride (bf16 elems)

__global__ __launch_bounds__(256) void attn_mma_kernel(const int* __restrict__ mask)
{
    extern __shared__ char dsm[];
    __nv_bfloat16* Ph = (__nv_bfloat16*)dsm;        // Q first, later P
    __nv_bfloat16* Pl = Ph + 64*AS;
    __nv_bfloat16* Kh = Pl + 64*AS;
    __nv_bfloat16* Kl = Kh + 64*AS;
    __nv_bfloat16* Vh = Kl + 64*AS;
    __nv_bfloat16* Vl = Vh + 64*AS;
    float* red_mx = (float*)(Vl + 64*AS);           // [4 m_w][2 n_w][16 rows]
    float* red_sm = red_mx + 128;

    const int q0 = blockIdx.x * 64, h = blockIdx.y, b = blockIdx.z;
    const int tid = threadIdx.x, lane = tid & 31, wid = tid >> 5;
    const int m_w = wid >> 1, n_w = wid & 1;
    const int m_off = m_w * 16, n_off = n_w * 32;
    const int r = lane >> 2, c2 = (lane & 3) * 2;
    const int lrow = lane & 15, lcol = (lane >> 4) << 3;

    const size_t base = ((size_t)b*H_ + h) * S_ * D_;
    const __nv_bfloat16 *Qh = g_qh + base, *Ql = g_ql + base;
    const __nv_bfloat16 *Kgh = g_kh + base, *Kgl = g_kl + base;
    const __nv_bfloat16 *Vgh = g_vh + base, *Vgl = g_vl + base;
    const int* Mb = mask + (size_t)b * S_ * S_;

    const unsigned sPh = smem_u32(Ph), sPl = smem_u32(Pl);
    const unsigned sKh = smem_u32(Kh), sKl = smem_u32(Kl);
    const unsigned sVh = smem_u32(Vh), sVl = smem_u32(Vl);

    const int t_r0 = tid >> 3;            // 0..31
    const int t_d  = (tid & 7) * 8;       // 0..56

    {
        size_t o0 = (size_t)(q0 + t_r0) * D_ + t_d;
        size_t o1 = (size_t)(q0 + t_r0 + 32) * D_ + t_d;
        *(uint4*)(Ph + t_r0*AS + t_d)      = *(const uint4*)(Qh + o0);
        *(uint4*)(Pl + t_r0*AS + t_d)      = *(const uint4*)(Ql + o0);
        *(uint4*)(Ph + (t_r0+32)*AS + t_d) = *(const uint4*)(Qh + o1);
        *(uint4*)(Pl + (t_r0+32)*AS + t_d) = *(const uint4*)(Ql + o1);
    }
    __syncthreads();
    unsigned qh[4][4], ql[4][4];
    #pragma unroll
    for (int ks = 0; ks < 4; ks++) {
        unsigned off = (unsigned)(((m_off + lrow)*AS + ks*16 + lcol) * 2);
        ldsm4(qh[ks], sPh + off);
        ldsm4(ql[ks], sPl + off);
    }
    __syncthreads();

    float o[4][4] = {};
    float mi0 = -1e30f, mi1 = -1e30f, li0 = 0.f, li1 = 0.f;

    for (int k0 = 0; k0 < S_; k0 += 64) {
        __syncthreads();
        {
            size_t o0 = (size_t)(k0 + t_r0) * D_ + t_d;
            size_t o1 = (size_t)(k0 + t_r0 + 32) * D_ + t_d;
            *(uint4*)(Kh + t_r0*AS + t_d)      = *(const uint4*)(Kgh + o0);
            *(uint4*)(Kl + t_r0*AS + t_d)      = *(const uint4*)(Kgl + o0);
            *(uint4*)(Kh + (t_r0+32)*AS + t_d) = *(const uint4*)(Kgh + o1);
            *(uint4*)(Kl + (t_r0+32)*AS + t_d) = *(const uint4*)(Kgl + o1);
            *(uint4*)(Vh + t_r0*AS + t_d)      = *(const uint4*)(Vgh + o0);
            *(uint4*)(Vl + t_r0*AS + t_d)      = *(const uint4*)(Vgl + o0);
            *(uint4*)(Vh + (t_r0+32)*AS + t_d) = *(const uint4*)(Vgh + o1);
            *(uint4*)(Vl + (t_r0+32)*AS + t_d) = *(const uint4*)(Vgl + o1);
        }
        __syncthreads();

        float s[4][4] = {};
        #pragma unroll
        for (int ks = 0; ks < 4; ks++) {
            unsigned bh[2][4], bl[2][4];
            #pragma unroll
            for (int g = 0; g < 2; g++) {
                unsigned off = (unsigned)(((n_off + g*16 + lrow)*AS + ks*16 + lcol) * 2);
                ldsm4(bh[g], sKh + off);
                ldsm4(bl[g], sKl + off);
            }
            #pragma unroll
            for (int nf = 0; nf < 4; nf++) {
                unsigned b0h = bh[nf>>1][nf&1], b1h = bh[nf>>1][2+(nf&1)];
                unsigned b0l = bl[nf>>1][nf&1], b1l = bl[nf>>1][2+(nf&1)];
                mma_bf16(s[nf], qh[ks], b0h, b1h);
                mma_bf16(s[nf], qh[ks], b0l, b1l);
                mma_bf16(s[nf], ql[ks], b0h, b1h);
            }
        }

        const int row0g = q0 + m_off + r;
        float mx0 = -1e30f, mx1 = -1e30f;
        #pragma unroll
        for (int nf = 0; nf < 4; nf++) {
            int colg = k0 + n_off + nf*8 + c2;
            int2 mv0 = *(const int2*)(Mb + (size_t)row0g*S_ + colg);
            int2 mv1 = *(const int2*)(Mb + (size_t)(row0g+8)*S_ + colg);
            s[nf][0] = mv0.x ? s[nf][0]*0.125f : -1e9f;
            s[nf][1] = mv0.y ? s[nf][1]*0.125f : -1e9f;
            s[nf][2] = mv1.x ? s[nf][2]*0.125f : -1e9f;
            s[nf][3] = mv1.y ? s[nf][3]*0.125f : -1e9f;
            mx0 = fmaxf(mx0, fmaxf(s[nf][0], s[nf][1]));
            mx1 = fmaxf(mx1, fmaxf(s[nf][2], s[nf][3]));
        }
        mx0 = fmaxf(mx0, __shfl_xor_sync(0xffffffffu, mx0, 1));
        mx0 = fmaxf(mx0, __shfl_xor_sync(0xffffffffu, mx0, 2));
        mx1 = fmaxf(mx1, __shfl_xor_sync(0xffffffffu, mx1, 1));
        mx1 = fmaxf(mx1, __shfl_xor_sync(0xffffffffu, mx1, 2));
        if ((lane & 3) == 0) {
            red_mx[m_w*32 + n_w*16 + r]     = mx0;
            red_mx[m_w*32 + n_w*16 + r + 8] = mx1;
        }
        __syncthreads();
        float cm0 = fmaxf(red_mx[m_w*32 + r],     red_mx[m_w*32 + 16 + r]);
        float cm1 = fmaxf(red_mx[m_w*32 + r + 8], red_mx[m_w*32 + 24 + r]);

        float mn0 = fmaxf(mi0, cm0), mn1 = fmaxf(mi1, cm1);
        float f0 = __expf(mi0 - mn0), f1 = __expf(mi1 - mn1);
        mi0 = mn0; mi1 = mn1;

        float sm0 = 0.f, sm1 = 0.f;
        #pragma unroll
        for (int nf = 0; nf < 4; nf++) {
            float p0 = __expf(s[nf][0] - mn0), p1 = __expf(s[nf][1] - mn0);
            float p2 = __expf(s[nf][2] - mn1), p3 = __expf(s[nf][3] - mn1);
            sm0 += p0 + p1; sm1 += p2 + p3;
            int col = n_off + nf*8 + c2;
            unsigned hi, lo;
            split_pair(p0, p1, hi, lo);
            *(unsigned*)(Ph + (m_off + r)*AS + col) = hi;
            *(unsigned*)(Pl + (m_off + r)*AS + col) = lo;
            split_pair(p2, p3, hi, lo);
            *(unsigned*)(Ph + (m_off + r + 8)*AS + col) = hi;
            *(unsigned*)(Pl + (m_off + r + 8)*AS + col) = lo;
        }
        sm0 += __shfl_xor_sync(0xffffffffu, sm0, 1);
        sm0 += __shfl_xor_sync(0xffffffffu, sm0, 2);
        sm1 += __shfl_xor_sync(0xffffffffu, sm1, 1);
        sm1 += __shfl_xor_sync(0xffffffffu, sm1, 2);
        if ((lane & 3) == 0) {
            red_sm[m_w*32 + n_w*16 + r]     = sm0;
            red_sm[m_w*32 + n_w*16 + r + 8] = sm1;
        }
        __syncthreads();   // also publishes P for the PV mma
        li0 = li0*f0 + red_sm[m_w*32 + r]     + red_sm[m_w*32 + 16 + r];
        li1 = li1*f1 + red_sm[m_w*32 + r + 8] + red_sm[m_w*32 + 24 + r];

        #pragma unroll
        for (int df = 0; df < 4; df++) {
            o[df][0] *= f0; o[df][1] *= f0;
            o[df][2] *= f1; o[df][3] *= f1;
        }

        #pragma unroll
        for (int ks = 0; ks < 4; ks++) {
            unsigned ph4[4], pl4[4];
            unsigned aoff = (unsigned)(((m_off + lrow)*AS + ks*16 + lcol) * 2);
            ldsm4(ph4, sPh + aoff);
            ldsm4(pl4, sPl + aoff);
            unsigned vh[2][4], vl[2][4];
            #pragma unroll
            for (int g = 0; g < 2; g++) {
                unsigned boff = (unsigned)(((ks*16 + lrow)*AS + n_off + g*16 + lcol) * 2);
                ldsm4t(vh[g], sVh + boff);
                ldsm4t(vl[g], sVl + boff);
            }
            #pragma unroll
            for (int df = 0; df < 4; df++) {
                unsigned b0h = vh[df>>1][(df&1)*2], b1h = vh[df>>1][(df&1)*2 + 1];
                unsigned b0l = vl[df>>1][(df&1)*2], b1l = vl[df>>1][(df&1)*2 + 1];
                mma_bf16(o[df], ph4, b0h, b1h);
                mma_bf16(o[df], ph4, b0l, b1l);
                mma_bf16(o[df], pl4, b0h, b1h);
            }
        }
    }

    float inv0 = 1.f / li0, inv1 = 1.f / li1;
    int rowg0 = q0 + m_off + r;
    #pragma unroll
    for (int df = 0; df < 4; df++) {
        int col = n_off + df*8 + c2;
        size_t i0 = ((size_t)(b*S_ + rowg0))*E_ + h*D_ + col;
        size_t i1 = ((size_t)(b*S_ + rowg0 + 8))*E_ + h*D_ + col;
        unsigned hi, lo;
        split_pair(o[df][0]*inv0, o[df][1]*inv0, hi, lo);
        *(unsigned*)(g_ch + i0) = hi;
        *(unsigned*)(g_cl + i0) = lo;
        split_pair(o[df][2]*inv1, o[df][3]*inv1, hi, lo);
        *(unsigned*)(g_ch + i1) = hi;
        *(unsigned*)(g_cl + i1) = lo;
    }
}

#define ATTN_SMEM (6*64*AS*2 + 256*4)   // 55296 + 1024 = 56320

// ---------------------------------------------------------------------------
extern "C" void kernel_launch(void* const* d_in, const int* in_sizes, int n_in,
                              void* d_out, int out_size)
{
    const float* x    = (const float*)d_in[0];
    const int*   mask = (const int*)  d_in[1];
    const float* Wq   = (const float*)d_in[2];
    const float* bq   = (const float*)d_in[3];
    const float* Wk   = (const float*)d_in[4];
    const float* bk   = (const float*)d_in[5];
    const float* Wv   = (const float*)d_in[6];
    const float* bv   = (const float*)d_in[7];
    const float* Wo   = (const float*)d_in[8];
    const float* bo   = (const float*)d_in[9];
    float* out = (float*)d_out;

    cudaFuncSetAttribute(attn_mma_kernel,
        cudaFuncAttributeMaxDynamicSharedMemorySize, ATTN_SMEM);
    cudaFuncSetAttribute(qkv_fused_kernel,
        cudaFuncAttributeMaxDynamicSharedMemorySize, GEMM_SMEM);
    cudaFuncSetAttribute(oproj_fused_kernel,
        cudaFuncAttributeMaxDynamicSharedMemorySize, GEMM_SMEM);

    cvt_x_kernel   <<<BS_*E_/4/256, 256>>>(x);
    cvt_wqkv_kernel<<<3*H_*D_*E_/4/256, 256>>>(Wq, Wk, Wv);
    cvt_wo_kernel  <<<E_*E_/4/256, 256>>>(Wo);

    dim3 gA(BS_/128, 3*E_/128);
    qkv_fused_kernel<<<gA, 256, GEMM_SMEM>>>(bq, bk, bv);

    dim3 gB(S_/64, H_, B_);
    attn_mma_kernel<<<gB, 256, ATTN_SMEM>>>(mask);

    dim3 gC(BS_/128, E_/128);
    oproj_fused_kernel<<<gC, 256, GEMM_SMEM>>>(bo, out);
}